// round 1
// baseline (speedup 1.0000x reference)
#include <cuda_runtime.h>
#include <stdint.h>

// out[b, 0, i, 0] = state_real[b, rev12(i)]
// out[b, 1, i, 0] = state_imag[b, rev12(i)]
// rev12(i) = __brev(i) >> 20  (12-bit bit reversal)
//
// One CTA per (b, part) vector of 4096 floats. Writes are float4 (coalesced
// STG.128); the 4 source elements for out[i..i+3] sit at r, r+2048, r+1024,
// r+3072 (bit-reversal of the low 2 bits of i lands in bits 11..10).
// The 16 KB source vector becomes L1-resident, so the scattered reads cost
// only compulsory DRAM traffic.

#define NQ 12
#define NSTATE (1 << NQ)        // 4096
#define THREADS 256
#define V4_PER_VEC (NSTATE / 4) // 1024

__global__ __launch_bounds__(THREADS)
void qft_bitrev_kernel(const float* __restrict__ state_real,
                       const float* __restrict__ state_imag,
                       float* __restrict__ out)
{
    const int bp   = blockIdx.x;        // 0 .. 2*BATCH-1
    const int b    = bp >> 1;
    const int part = bp & 1;

    const float* __restrict__ src = (part == 0) ? (state_real + (size_t)b * NSTATE)
                                                : (state_imag + (size_t)b * NSTATE);
    float* __restrict__ dst = out + (size_t)bp * NSTATE;   // [B,2,N,1] flat: (b*2+part)*N

    #pragma unroll
    for (int t = threadIdx.x; t < V4_PER_VEC; t += THREADS) {
        const int i0 = t << 2;                       // i0 % 4 == 0
        const int r  = (int)(__brev((unsigned)i0) >> (32 - NQ));  // bits 11..10 are 0
        float4 v;
        v.x = src[r];
        v.y = src[r + 2048];
        v.z = src[r + 1024];
        v.w = src[r + 3072];
        *reinterpret_cast<float4*>(dst + i0) = v;
    }
}

extern "C" void kernel_launch(void* const* d_in, const int* in_sizes, int n_in,
                              void* d_out, int out_size)
{
    // metadata order: matrix (unused — it is exactly the 12-bit bit-reversal
    // permutation), state_real [256,4096,1], state_imag [256,4096,1]
    const float* state_real = (const float*)d_in[1];
    const float* state_imag = (const float*)d_in[2];
    float* out = (float*)d_out;

    const int batch = in_sizes[1] / NSTATE;   // 256
    qft_bitrev_kernel<<<batch * 2, THREADS>>>(state_real, state_imag, out);
}

// round 2
// speedup vs baseline: 1.8653x; 1.8653x over previous
#include <cuda_runtime.h>
#include <stdint.h>

// out[b, p, i] = state_p[b, rev12(i)],  rev12(i) = __brev(i) >> 20.
//
// Round-1 kernel was L1-wavefront bound (58.6% L1, 7.8% DRAM): the gather's
// lane bits bit-reverse into address bits 9..5, so every warp-load touched 32
// distinct 128B lines. This version stages each 16 KB vector in shared memory:
//   phase 1: fully coalesced float4 loads, swizzled scalar STS
//   phase 2: swizzled scalar LDS (conflict-free), coalesced float4 STG
// Swizzle f(x) = x ^ (((x>>5) ^ (x>>7)) & 31) makes BOTH the linear-write and
// bit-reversed-read patterns 32-bank conflict-free (verified by the GF(2)
// lane->bank matrices; f is injective since it only XORs the low 5 bits with
// a function of bits >=5).

#define NQ       12
#define NSTATE   (1 << NQ)      // 4096
#define THREADS  256
#define PER_THR  (NSTATE / THREADS / 4)  // 4 float4 per thread

__device__ __forceinline__ int swz(int x) {
    return x ^ (((x >> 5) ^ (x >> 7)) & 31);
}

__global__ __launch_bounds__(THREADS)
void qft_bitrev_smem_kernel(const float* __restrict__ state_real,
                            const float* __restrict__ state_imag,
                            float* __restrict__ out)
{
    __shared__ float sv[NSTATE];

    const int bp   = blockIdx.x;          // 0 .. 2*BATCH-1
    const int b    = bp >> 1;
    const int part = bp & 1;

    const float* __restrict__ src = (part == 0) ? (state_real + (size_t)b * NSTATE)
                                                : (state_imag + (size_t)b * NSTATE);
    float* __restrict__ dst = out + (size_t)bp * NSTATE;  // [B,2,N,1] flat

    const int tid = threadIdx.x;

    // Phase 1: coalesced LDG.128, swizzled scalar STS (conflict-free)
    #pragma unroll
    for (int k = 0; k < PER_THR; k++) {
        const int t  = tid + k * THREADS;
        const int j0 = t << 2;
        const float4 v = *reinterpret_cast<const float4*>(src + j0);
        sv[swz(j0 + 0)] = v.x;
        sv[swz(j0 + 1)] = v.y;
        sv[swz(j0 + 2)] = v.z;
        sv[swz(j0 + 3)] = v.w;
    }

    __syncthreads();

    // Phase 2: swizzled scalar LDS (conflict-free), coalesced STG.128.
    // out[i0..i0+3] = sv[rev(i0)], sv[rev(i0)|2048], sv[rev(i0)|1024], sv[rev(i0)|3072]
    #pragma unroll
    for (int k = 0; k < PER_THR; k++) {
        const int t  = tid + k * THREADS;
        const int i0 = t << 2;                           // i0 % 4 == 0
        const int r  = (int)(__brev((unsigned)i0) >> (32 - NQ));  // bits 11..10 clear
        float4 v;
        v.x = sv[swz(r)];
        v.y = sv[swz(r | 2048)];
        v.z = sv[swz(r | 1024)];
        v.w = sv[swz(r | 3072)];
        *reinterpret_cast<float4*>(dst + i0) = v;
    }
}

extern "C" void kernel_launch(void* const* d_in, const int* in_sizes, int n_in,
                              void* d_out, int out_size)
{
    // metadata order: matrix (unused: it IS the 12-bit bit-reversal
    // permutation), state_real [256,4096,1], state_imag [256,4096,1]
    const float* state_real = (const float*)d_in[1];
    const float* state_imag = (const float*)d_in[2];
    float* out = (float*)d_out;

    const int batch = in_sizes[1] / NSTATE;   // 256
    qft_bitrev_smem_kernel<<<batch * 2, THREADS>>>(state_real, state_imag, out);
}

// round 3
// speedup vs baseline: 2.1762x; 1.1667x over previous
#include <cuda_runtime.h>
#include <stdint.h>

// out[b, p, i] = state_p[b, rev12(i)].
// Tile decomposition: r = u*128 + t*32 + v  (u,v in [0,32), t in [0,4))
//                 =>  i = rev5(v)*128 + rev2(t)*32 + rev5(u)
// Each (b, part, t) tile is a self-contained 1024-element permutation:
// one 128-thread CTA per tile => grid 2048 (vs 512 before), fixing the
// occupancy/latency bound seen in round 2 (occ 37%, DRAM 15%).
//
// smem placement: tile[u*32 + (v ^ (u&3) ^ ((u&7)<<2))]
// -> conflict-free banks for BOTH the linear STS and bit-reversed LDS phases
// (lane->bank maps are invertible GF(2) matrices in both; see analysis).

#define NQ      12
#define NSTATE  (1 << NQ)   // 4096
#define THREADS 128

__device__ __forceinline__ int rev5(int v) { return (int)(__brev((unsigned)v) >> 27); }
__device__ __forceinline__ int rev3(int v) { return (int)(__brev((unsigned)v) >> 29); }
__device__ __forceinline__ int swz(int u, int v) {
    return u * 32 + (v ^ (u & 3) ^ ((u & 7) << 2));
}

__global__ __launch_bounds__(THREADS)
void qft_bitrev_tile_kernel(const float* __restrict__ state_real,
                            const float* __restrict__ state_imag,
                            float* __restrict__ out)
{
    __shared__ float tile[32 * 32];

    const int blk  = blockIdx.x;          // b*8 + part*4 + t
    const int t    = blk & 3;
    const int part = (blk >> 2) & 1;
    const int b    = blk >> 3;

    const float* __restrict__ src = (part == 0) ? (state_real + (size_t)b * NSTATE)
                                                : (state_imag + (size_t)b * NSTATE);
    float* __restrict__ dst = out + ((size_t)b * 2 + part) * NSTATE;

    const int tid   = threadIdx.x;
    const int rgt32 = t * 32;            // r-offset of this tile
    const int igt32 = (((t & 1) << 1) | (t >> 1)) * 32;   // rev2(t)*32

    // Phase 1: coalesced LDG.128 along v, swizzled STS.
    // p in [0,256): u = p>>3, x = p&7, v = 4x..4x+3
    #pragma unroll
    for (int q = 0; q < 2; q++) {
        const int p = tid + q * THREADS;
        const int u = p >> 3;
        const int x = p & 7;
        const float4 val = *reinterpret_cast<const float4*>(src + u * 128 + rgt32 + 4 * x);
        tile[swz(u, 4 * x + 0)] = val.x;
        tile[swz(u, 4 * x + 1)] = val.y;
        tile[swz(u, 4 * x + 2)] = val.z;
        tile[swz(u, 4 * x + 3)] = val.w;
    }

    __syncthreads();

    // Phase 2: swizzled LDS (bit-reversed gather), coalesced STG.128.
    // p in [0,256): v = p>>3, x = p&7; output i0 = rev5(v)*128 + rev2(t)*32 + 4x
    // component c reads u_c = rev3(x) + {0,16,8,24}[c]
    #pragma unroll
    for (int q = 0; q < 2; q++) {
        const int p  = tid + q * THREADS;
        const int v  = p >> 3;
        const int x  = p & 7;
        const int r3 = rev3(x);
        float4 val;
        val.x = tile[swz(r3 +  0, v)];
        val.y = tile[swz(r3 + 16, v)];
        val.z = tile[swz(r3 +  8, v)];
        val.w = tile[swz(r3 + 24, v)];
        *reinterpret_cast<float4*>(dst + rev5(v) * 128 + igt32 + 4 * x) = val;
    }
}

extern "C" void kernel_launch(void* const* d_in, const int* in_sizes, int n_in,
                              void* d_out, int out_size)
{
    // metadata order: matrix (unused: it IS the 12-bit bit-reversal
    // permutation), state_real [256,4096,1], state_imag [256,4096,1]
    const float* state_real = (const float*)d_in[1];
    const float* state_imag = (const float*)d_in[2];
    float* out = (float*)d_out;

    const int batch = in_sizes[1] / NSTATE;   // 256
    qft_bitrev_tile_kernel<<<batch * 2 * 4, THREADS>>>(state_real, state_imag, out);
}

// round 4
// speedup vs baseline: 2.2077x; 1.0145x over previous
#include <cuda_runtime.h>
#include <stdint.h>

// out[b, p, i] = state_p[b, rev12(i)].
// Tile decomposition: r = u*128 + t*32 + v  (u,v in [0,32), t in [0,4))
//                 =>  i = rev5(v)*128 + rev2(t)*32 + rev5(u)
// One 128-thread CTA per (b, part, t) tile (grid 2048).
//
// smem layout: tile[u*32 + (v ^ ((u&7)<<2))] — XORs only bits 2..4 of v, so:
//   * phase 1 is a single STS.128 per float4 (components keep their order,
//     16B-aligned); 16B-group = x ^ (u&7), bijective per 8-lane phase.
//   * phase 2 scalar LDS banks = (lane>>3, rev3(x)), bijective over the warp.
//   * gather components u_c = rev3(x)+{0,16,8,24} all have u_c&7 == rev3(x),
//     so their addresses are one base + {0,512,256,768} floats (imm offsets).
// Both phases bank-conflict-free; both global sides 128B-coalesced.

#define NQ      12
#define NSTATE  (1 << NQ)   // 4096
#define THREADS 128

__device__ __forceinline__ int rev5(int v) { return (int)(__brev((unsigned)v) >> 27); }
__device__ __forceinline__ int rev3(int v) { return (int)(__brev((unsigned)v) >> 29); }

__global__ __launch_bounds__(THREADS)
void qft_bitrev_tile_kernel(const float* __restrict__ state_real,
                            const float* __restrict__ state_imag,
                            float* __restrict__ out)
{
    __shared__ float tile[32 * 32];

    const int blk  = blockIdx.x;          // b*8 + part*4 + t
    const int t    = blk & 3;
    const int part = (blk >> 2) & 1;
    const int b    = blk >> 3;

    const float* __restrict__ src =
        ((part == 0) ? state_real : state_imag) + (size_t)b * NSTATE + t * 32;
    float* __restrict__ dst =
        out + ((size_t)b * 2 + part) * NSTATE + ((((t & 1) << 1) | (t >> 1)) * 32);

    const int tid = threadIdx.x;

    // Phase 1: coalesced LDG.128 along v, swizzled STS.128.
    // p in [0,256): u = p>>3, x = p&7, v = 4x..4x+3
    #pragma unroll
    for (int q = 0; q < 2; q++) {
        const int p = tid + q * THREADS;
        const int u = p >> 3;
        const int x = p & 7;
        const float4 val = *reinterpret_cast<const float4*>(src + u * 128 + 4 * x);
        *reinterpret_cast<float4*>(tile + u * 32 + ((4 * x) ^ ((u & 7) << 2))) = val;
    }

    __syncthreads();

    // Phase 2: conflict-free scalar LDS gather (the transpose), coalesced STG.128.
    // p in [0,256): v = p>>3, x = p&7; output i0 = rev5(v)*128 + rev2(t)*32 + 4x
    // component d reads u_d = rev3(x) + {0,16,8,24}[d]
    #pragma unroll
    for (int q = 0; q < 2; q++) {
        const int p  = tid + q * THREADS;
        const int v  = p >> 3;
        const int x  = p & 7;
        const int r3 = rev3(x);
        const float* __restrict__ basep = tile + r3 * 32 + (v ^ (r3 << 2));
        float4 val;
        val.x = basep[0];
        val.y = basep[512];
        val.z = basep[256];
        val.w = basep[768];
        *reinterpret_cast<float4*>(dst + rev5(v) * 128 + 4 * x) = val;
    }
}

extern "C" void kernel_launch(void* const* d_in, const int* in_sizes, int n_in,
                              void* d_out, int out_size)
{
    // metadata order: matrix (unused: it IS the 12-bit bit-reversal
    // permutation), state_real [256,4096,1], state_imag [256,4096,1]
    const float* state_real = (const float*)d_in[1];
    const float* state_imag = (const float*)d_in[2];
    float* out = (float*)d_out;

    const int batch = in_sizes[1] / NSTATE;   // 256
    qft_bitrev_tile_kernel<<<batch * 2 * 4, THREADS>>>(state_real, state_imag, out);
}